// round 7
// baseline (speedup 1.0000x reference)
#include <cuda_runtime.h>
#include <cuda_bf16.h>

#define N_    4096
#define FIN_  500
#define H_    64
#define C_    7
#define E_    65536
#define B_    1024
#define A_    20
#define NW_   128          // bitset words per row
#define CH_   (C_*H_)      // 448
#define HB_   65536        // 16-bit histogram bins
#define CAP_  4096
#define NT_   256
#define KB_   50
#define NSTG_ (FIN_/KB_)   // 10
#define ADJB_ 32
#define KSEL_ (E_/2)

// ---------------- device scratch (zero at module load) ----------------------
__device__ float    g_embed[N_*H_];
__device__ unsigned g_adj[N_*NW_];
__device__ int      g_cls[N_];
__device__ int      g_hist[HB_];
__device__ unsigned g_cand[CAP_];
__device__ int      g_ncand;
__device__ unsigned g_barcnt;
__device__ unsigned g_bargen;
// fallback-only scratch
__device__ float    g_thresh;
__device__ float    g_red[3*B_*CH_];

// ---------------- packed f32x2 helpers --------------------------------------
__device__ __forceinline__ unsigned long long pack2(float lo, float hi) {
    unsigned long long v;
    asm("mov.b64 %0, {%1, %2};" : "=l"(v) : "f"(lo), "f"(hi));
    return v;
}
__device__ __forceinline__ void unpack2(unsigned long long v, float& lo, float& hi) {
    asm("mov.b64 {%0, %1}, %2;" : "=f"(lo), "=f"(hi) : "l"(v));
}
__device__ __forceinline__ void fma2(unsigned long long& d,
                                     unsigned long long a, unsigned long long b) {
    asm("fma.rn.f32x2 %0, %1, %2, %0;" : "+l"(d) : "l"(a), "l"(b));
}

// ---------------- shared-memory union (max 32.4 KB) --------------------------
struct EncSm  { float xs[2][KB_][17]; float ws[2][KB_][64]; };          // 32400 B
struct PickSm { int scan[NT_]; unsigned cand[CAP_]; };                  // 17408 B
struct ClsSm  { float sa[C_][64]; float sa2[C_]; float swp[CH_]; float sbp[C_]; };
struct CmSm   { unsigned hop[NW_]; int list1[1024]; int list[4096];
                float sums[3][CH_]; int cnt[3][C_]; int n1, nlist;
                float op[CH_]; float on[CH_]; float part[8][32]; };     // ~31 KB
union MegaSm  { EncSm enc; PickSm pick; ClsSm cls; CmSm cm; };

// ---------------- grid-wide barrier (all blocks resident by construction) ----
__device__ __forceinline__ void gridbar(unsigned& gen, int nb) {
    __syncthreads();
    if (threadIdx.x == 0) {
        __threadfence();                               // release block's writes
        if (atomicAdd(&g_barcnt, 1u) == (unsigned)nb - 1u) {
            g_barcnt = 0u;
            __threadfence();
            *(volatile unsigned*)&g_bargen = gen + 1u;
        } else {
            while (*(volatile unsigned*)&g_bargen == gen) __nanosleep(64);
        }
    }
    __syncthreads();
    __threadfence();                                   // acquire
    gen += 1u;
}

// ================= mega-kernel: whole pipeline, one launch ===================
__global__ void __launch_bounds__(NT_, 2) k_mega(
    const float* __restrict__ x, const int* __restrict__ ei,
    const int* __restrict__ ego, const int* __restrict__ pos,
    const int* __restrict__ neg, const float* __restrict__ ew,
    const int* __restrict__ aidx, const float* __restrict__ Wenc,
    const float* __restrict__ benc, const float* __restrict__ Wpred,
    const float* __restrict__ bpred, const float* __restrict__ W1,
    const float* __restrict__ b1, const float* __restrict__ W2,
    const float* __restrict__ b2, float* __restrict__ out, int nb)
{
    __shared__ MegaSm sm;
    __shared__ int s_bucket, s_krem;
    __shared__ float s_thresh;
    int tid = threadIdx.x, bid = blockIdx.x;
    int lane = tid & 31, warp = tid >> 5;
    unsigned gen = *(volatile unsigned*)&g_bargen;
    int gthreads = nb * NT_;
    int g = bid * NT_ + tid;

    // ---- P1: histogram + zero adjacency + reset candidate counter ----------
    for (int i = g; i < E_; i += gthreads)
        atomicAdd(&g_hist[__float_as_uint(ew[i]) >> 16], 1);
    {
        uint4 z = make_uint4(0u, 0u, 0u, 0u);
        for (int i = g; i < (N_*NW_)/4; i += gthreads) ((uint4*)g_adj)[i] = z;
    }
    if (g == 0) g_ncand = 0;
    gridbar(gen, nb);

    // ---- P2: per-block redundant hist scan -> bucket, then candidate gather -
    {
        const int CHK = HB_ / NT_;          // 256 bins/thread, descending
        int base = HB_ - 1 - tid * CHK;
        int psum = 0;
#pragma unroll 8
        for (int i = 0; i < CHK; i++) psum += g_hist[base - i];
        sm.pick.scan[tid] = psum;
        __syncthreads();
        for (int off = 1; off < NT_; off <<= 1) {
            int v = (tid >= off) ? sm.pick.scan[tid - off] : 0;
            __syncthreads();
            sm.pick.scan[tid] += v;
            __syncthreads();
        }
        int incl = sm.pick.scan[tid], excl = incl - psum;
        if (excl < KSEL_ && incl >= KSEL_) {
            int cum = excl;
            for (int i = 0; i < CHK; i++) {
                int bb = base - i, h = g_hist[bb];
                cum += h;
                if (cum >= KSEL_) { s_bucket = bb; s_krem = KSEL_ - (cum - h); break; }
            }
        }
        __syncthreads();
        int bucket = s_bucket;
        int chunk = (E_ + nb - 1) / nb;
        int lo = bid * chunk, hi = min(lo + chunk, E_);
        for (int i = lo + tid; i < hi; i += NT_) {
            unsigned key = __float_as_uint(ew[i]);
            if ((int)(key >> 16) == bucket) {
                int p = atomicAdd(&g_ncand, 1);
                if (p < CAP_) g_cand[p] = key;
            }
        }
    }
    gridbar(gen, nb);

    // ---- P3: split roles: encoder tiles vs (threshold + adj + hist rezero) --
    if (bid >= nb - ADJB_) {
        int nc = g_ncand; if (nc > CAP_) nc = CAP_;
        for (int i = tid; i < nc; i += NT_) sm.pick.cand[i] = g_cand[i];
        __syncthreads();
        int krem = s_krem;
        for (int i = tid; i < nc; i += NT_) {
            unsigned v = sm.pick.cand[i];
            int gt = 0, eq = 0;
            for (int j = 0; j < nc; j++) {
                unsigned u = sm.pick.cand[j];
                gt += (u > v); eq += (u == v);
            }
            if (gt < krem && krem <= gt + eq) s_thresh = __uint_as_float(v);
        }
        __syncthreads();
        float th = s_thresh;
        int a0 = (bid - (nb - ADJB_)) * NT_ + tid;
        for (int i = a0; i < E_ + N_; i += ADJB_ * NT_) {
            if (i < E_) {
                if (ew[i] >= th) {
                    int s = ei[i], d = ei[E_ + i];
                    atomicOr(&g_adj[s*NW_ + (d >> 5)], 1u << (d & 31));
                }
            } else {
                int n = i - E_;
                atomicOr(&g_adj[n*NW_ + (n >> 5)], 1u << (n & 31));   // diag
            }
        }
        for (int i = a0; i < HB_; i += ADJB_ * NT_) g_hist[i] = 0;    // for replay
    } else {
        // encoder: 16-row x 64-col tiles; thread = 1 row x 4 cols; 2 FFMA2/kk
        int estride = nb - ADJB_;
        int row = tid & 15, colg = tid >> 4, c0 = colg * 4;
        for (int t = bid; t < N_/16; t += estride) {
            int r0 = t * 16;
            unsigned long long acc0 = 0ull, acc1 = 0ull;
            float xr[4]; float4 wr[4];
            // prologue: stage 0 (x: 800 scalars, w: 800 float4)
#pragma unroll
            for (int j = 0; j < 4; j++) {
                int i = tid + j*NT_;
                if (i < 800) {
                    xr[j] = x[(r0 + i/KB_)*FIN_ + (i % KB_)];
                    wr[j] = *(const float4*)&Wenc[(i >> 4)*H_ + (i & 15)*4];
                }
            }
#pragma unroll
            for (int j = 0; j < 4; j++) {
                int i = tid + j*NT_;
                if (i < 800) {
                    sm.enc.xs[0][i % KB_][i / KB_] = xr[j];
                    *(float4*)&sm.enc.ws[0][i >> 4][(i & 15)*4] = wr[j];
                }
            }
            __syncthreads();
            for (int s = 0; s < NSTG_; s++) {
                int buf = s & 1;
                if (s + 1 < NSTG_) {
                    int k0 = (s + 1) * KB_;
#pragma unroll
                    for (int j = 0; j < 4; j++) {
                        int i = tid + j*NT_;
                        if (i < 800) {
                            xr[j] = x[(r0 + i/KB_)*FIN_ + k0 + (i % KB_)];
                            wr[j] = *(const float4*)&Wenc[(k0 + (i >> 4))*H_ + (i & 15)*4];
                        }
                    }
                }
#pragma unroll 10
                for (int kk = 0; kk < KB_; kk++) {
                    float a = sm.enc.xs[buf][kk][row];
                    unsigned long long aa = pack2(a, a);
                    float4 bv = *(const float4*)&sm.enc.ws[buf][kk][c0];
                    fma2(acc0, aa, pack2(bv.x, bv.y));
                    fma2(acc1, aa, pack2(bv.z, bv.w));
                }
                if (s + 1 < NSTG_) {
                    int nbuf = buf ^ 1;
#pragma unroll
                    for (int j = 0; j < 4; j++) {
                        int i = tid + j*NT_;
                        if (i < 800) {
                            sm.enc.xs[nbuf][i % KB_][i / KB_] = xr[j];
                            *(float4*)&sm.enc.ws[nbuf][i >> 4][(i & 15)*4] = wr[j];
                        }
                    }
                }
                __syncthreads();
            }
            float v0, v1, v2, v3;
            unpack2(acc0, v0, v1); unpack2(acc1, v2, v3);
            v0 += benc[c0];   v1 += benc[c0+1];
            v2 += benc[c0+2]; v3 += benc[c0+3];
            *(float4*)&g_embed[(r0 + row)*H_ + c0] =
                make_float4(fmaxf(v0,0.f), fmaxf(v1,0.f), fmaxf(v2,0.f), fmaxf(v3,0.f));
        }
    }
    gridbar(gen, nb);

    // ---- P4: anchors + class assignment + log_softmax (blocks 0..15) -------
    if (bid < N_/NT_) {
        if (tid < 64) {
            for (int c = 0; c < C_; c++) {
                float s = 0.f;
#pragma unroll 4
                for (int a = 0; a < A_; a++) s += g_embed[aidx[c*A_ + a]*H_ + tid];
                sm.cls.sa[c][tid] = s * (1.f / A_);
            }
        } else {
            for (int i = tid - 64; i < CH_; i += NT_ - 64) sm.cls.swp[i] = Wpred[i];
            if (tid - 64 < C_) sm.cls.sbp[tid - 64] = bpred[tid - 64];
        }
        __syncthreads();
        if (tid < C_) {
            float s = 0.f;
            for (int h = 0; h < H_; h++) { float v = sm.cls.sa[tid][h]; s += v*v; }
            sm.cls.sa2[tid] = s;
        }
        __syncthreads();
        int n = bid * NT_ + tid;
        float dot[C_], xo[C_];
        float en2 = 0.f;
#pragma unroll
        for (int c = 0; c < C_; c++) { dot[c] = 0.f; xo[c] = sm.cls.sbp[c]; }
        const float4* ep = (const float4*)(g_embed + n*H_);
#pragma unroll
        for (int i = 0; i < 16; i++) {
            float4 e4 = ep[i];
            en2 += e4.x*e4.x + e4.y*e4.y + e4.z*e4.z + e4.w*e4.w;
#pragma unroll
            for (int c = 0; c < C_; c++) {
                dot[c] += e4.x*sm.cls.sa[c][4*i]   + e4.y*sm.cls.sa[c][4*i+1]
                        + e4.z*sm.cls.sa[c][4*i+2] + e4.w*sm.cls.sa[c][4*i+3];
                xo[c]  += e4.x*sm.cls.swp[(4*i)*C_ + c]   + e4.y*sm.cls.swp[(4*i+1)*C_ + c]
                        + e4.z*sm.cls.swp[(4*i+2)*C_ + c] + e4.w*sm.cls.swp[(4*i+3)*C_ + c];
            }
        }
        int best = 0; float bd = 3.4e38f;
#pragma unroll
        for (int c = 0; c < C_; c++) {
            float d2 = en2 - 2.f*dot[c] + sm.cls.sa2[c];
            if (d2 < bd) { bd = d2; best = c; }
        }
        g_cls[n] = best;
        float m = xo[0];
#pragma unroll
        for (int c = 1; c < C_; c++) m = fmaxf(m, xo[c]);
        float se = 0.f;
#pragma unroll
        for (int c = 0; c < C_; c++) se += expf(xo[c] - m);
        float ls = logf(se);
#pragma unroll
        for (int c = 0; c < C_; c++) out[2*B_ + n*C_ + c] = xo[c] - m - ls;
    }
    gridbar(gen, nb);

    // ---- P5: fused 2-hop + class-mean triplet + decoder ---------------------
    for (int b = bid; b < B_; b += nb) {
        for (int t = 0; t < 3; t++) {
            int v = (t == 0) ? ego[b] : (t == 1) ? pos[b] : neg[b];
            for (int i = tid; i < CH_; i += NT_) sm.cm.sums[t][i] = 0.f;
            if (tid < C_) sm.cm.cnt[t][tid] = 0;
            if (tid == 0) { sm.cm.n1 = 0; sm.cm.nlist = 0; }
            if (tid < NW_) sm.cm.hop[tid] = g_adj[v*NW_ + tid];
            __syncthreads();
            if (tid < NW_) {
                unsigned bits = sm.cm.hop[tid];
                while (bits) {
                    int bb = __ffs(bits) - 1; bits &= bits - 1;
                    sm.cm.list1[atomicAdd(&sm.cm.n1, 1)] = tid*32 + bb;
                }
            }
            __syncthreads();
            int m1 = sm.cm.n1;
            if (tid < NW_) {
                unsigned acc = sm.cm.hop[tid];
                for (int j = 0; j < m1; j++) acc |= g_adj[sm.cm.list1[j]*NW_ + tid];
                sm.cm.hop[tid] = acc;
            }
            __syncthreads();
            if (tid < NW_) {
                unsigned bits = sm.cm.hop[tid];
                while (bits) {
                    int bb = __ffs(bits) - 1; bits &= bits - 1;
                    sm.cm.list[atomicAdd(&sm.cm.nlist, 1)] = tid*32 + bb;
                }
            }
            __syncthreads();
            int M = sm.cm.nlist;
            for (int li = warp; li < M; li += 8) {
                int n = sm.cm.list[li];
                int c = g_cls[n];
                float2 e2 = *(const float2*)&g_embed[n*H_ + lane*2];
                atomicAdd(&sm.cm.sums[t][c*H_ + lane*2],     e2.x);
                atomicAdd(&sm.cm.sums[t][c*H_ + lane*2 + 1], e2.y);
                if (lane == 0) atomicAdd(&sm.cm.cnt[t][c], 1);
            }
            __syncthreads();
        }
        for (int i = tid; i < CH_; i += NT_) {
            int c = i >> 6;
            float ce = (float)max(sm.cm.cnt[0][c], 1);
            float cp = (float)max(sm.cm.cnt[1][c], 1);
            float cn = (float)max(sm.cm.cnt[2][c], 1);
            float e  = sm.cm.sums[0][i] / ce;
            float p  = sm.cm.sums[1][i] / cp;
            float nn = sm.cm.sums[2][i] / cn;
            float dp = e - p, dn = e - nn;
            sm.cm.op[i] = dp*dp;
            sm.cm.on[i] = dn*dn;
        }
        __syncthreads();
        {
            const float* o = (warp < 4) ? sm.cm.op : sm.cm.on;
            int i0 = (warp & 3) * 112;
            float h = 0.f;
            for (int i = i0; i < i0 + 112; i++) h += o[i] * W1[i*32 + lane];
            sm.cm.part[warp][lane] = h;
        }
        __syncthreads();
        if (warp == 0 || warp == 4) {
            int pb = warp;
            float hv = sm.cm.part[pb][lane] + sm.cm.part[pb+1][lane]
                     + sm.cm.part[pb+2][lane] + sm.cm.part[pb+3][lane] + b1[lane];
            hv = fmaxf(hv, 0.f);
            float vv = hv * W2[lane];
#pragma unroll
            for (int o2 = 16; o2 > 0; o2 >>= 1)
                vv += __shfl_down_sync(0xffffffffu, vv, o2);
            if (lane == 0) out[(warp == 0) ? b : (B_ + b)] = vv + b2[0];
        }
        __syncthreads();
    }
}

// ================= fallback kernels (round-6 path, sequential) ===============
__global__ void k_hist_f(const float* __restrict__ w) {
    int i = blockIdx.x * blockDim.x + threadIdx.x;
    unsigned key = __float_as_uint(w[i]);
    atomicAdd(&g_hist[key >> 16], 1);
    uint4 z = make_uint4(0u,0u,0u,0u);
    ((uint4*)g_adj)[i] = z;
    ((uint4*)g_adj)[i + 65536] = z;
}
__global__ void k_pick_f(const float* __restrict__ w, int k) {
    __shared__ int s_scan[1024];
    __shared__ unsigned s_cand[2048];
    __shared__ int s_n, s_bucket, s_krem;
    int tid = threadIdx.x;
    const int CHK = HB_ / 1024;
    int base = HB_ - 1 - tid * CHK;
    int psum = 0;
#pragma unroll 8
    for (int i = 0; i < CHK; i++) psum += g_hist[base - i];
    s_scan[tid] = psum;
    __syncthreads();
    for (int off = 1; off < 1024; off <<= 1) {
        int v = (tid >= off) ? s_scan[tid - off] : 0;
        __syncthreads();
        s_scan[tid] += v;
        __syncthreads();
    }
    int incl = s_scan[tid], excl = incl - psum;
    if (excl < k && incl >= k) {
        int cum = excl;
        for (int i = 0; i < CHK; i++) {
            int b = base - i, h = g_hist[b];
            cum += h;
            if (cum >= k) { s_bucket = b; s_krem = k - (cum - h); break; }
        }
    }
    if (tid == 0) s_n = 0;
    __syncthreads();
#pragma unroll 8
    for (int i = 0; i < CHK; i++) g_hist[base - i] = 0;
    int bucket = s_bucket;
    for (int i = tid; i < E_; i += 1024) {
        unsigned key = __float_as_uint(w[i]);
        if ((int)(key >> 16) == bucket) {
            int p = atomicAdd(&s_n, 1);
            if (p < 2048) s_cand[p] = key;
        }
    }
    __syncthreads();
    int n = s_n < 2048 ? s_n : 2048;
    int krem = s_krem;
    for (int i = tid; i < n; i += 1024) {
        unsigned v = s_cand[i];
        int gt = 0, eq = 0;
        for (int j = 0; j < n; j++) { unsigned u = s_cand[j]; gt += (u > v); eq += (u == v); }
        if (gt < krem && krem <= gt + eq) g_thresh = __uint_as_float(v);
    }
}
__global__ __launch_bounds__(256) void k_encoder_f(
        const float* __restrict__ x, const float* __restrict__ Wenc,
        const float* __restrict__ benc) {
    __shared__ float xs[KB_][33];
    __shared__ float ws[KB_][64];
    int tid = threadIdx.x, lane = tid & 31, wrp = tid >> 5;
    int col0 = wrp * 8, r0 = blockIdx.x * 32;
    unsigned long long acc[4];
#pragma unroll
    for (int c = 0; c < 4; c++) acc[c] = 0ull;
    for (int k0 = 0; k0 < FIN_; k0 += KB_) {
        for (int i = tid; i < 1600; i += 256) xs[i % KB_][i / KB_] = x[(r0 + i/KB_)*FIN_ + k0 + i%KB_];
        for (int i = tid; i < 800; i += 256)
            *(float4*)&ws[i >> 4][(i & 15)*4] = *(const float4*)&Wenc[(k0 + (i >> 4))*64 + (i & 15)*4];
        __syncthreads();
#pragma unroll 10
        for (int kk = 0; kk < KB_; kk++) {
            float a = xs[kk][lane];
            unsigned long long aa = pack2(a, a);
            float4 b0 = *(const float4*)&ws[kk][col0];
            float4 b1 = *(const float4*)&ws[kk][col0 + 4];
            fma2(acc[0], aa, pack2(b0.x, b0.y));
            fma2(acc[1], aa, pack2(b0.z, b0.w));
            fma2(acc[2], aa, pack2(b1.x, b1.y));
            fma2(acc[3], aa, pack2(b1.z, b1.w));
        }
        __syncthreads();
    }
    int r = r0 + lane;
#pragma unroll
    for (int c = 0; c < 4; c++) {
        float v0, v1; unpack2(acc[c], v0, v1);
        v0 += benc[col0 + 2*c]; v1 += benc[col0 + 2*c + 1];
        *(float2*)&g_embed[r*64 + col0 + 2*c] =
            make_float2(v0 > 0.f ? v0 : 0.f, v1 > 0.f ? v1 : 0.f);
    }
}
__global__ void k_adj_f(const int* __restrict__ ei, const float* __restrict__ ew) {
    int i = blockIdx.x * blockDim.x + threadIdx.x;
    float th = g_thresh;
    if (i < E_) {
        if (ew[i] >= th) {
            int s = ei[i], d = ei[E_ + i];
            atomicOr(&g_adj[s*NW_ + (d >> 5)], 1u << (d & 31));
        }
    } else if (i < E_ + N_) {
        int n = i - E_;
        atomicOr(&g_adj[n*NW_ + (n >> 5)], 1u << (n & 31));
    }
}
__global__ void k_cls_f(const int* __restrict__ aidx, const float* __restrict__ Wpred,
                        const float* __restrict__ bpred, float* __restrict__ out) {
    __shared__ float sa[C_][64]; __shared__ float sa2[C_];
    __shared__ float swp[64*C_]; __shared__ float sbp[C_];
    int tid = threadIdx.x;
    if (tid < 64) {
        for (int c = 0; c < C_; c++) {
            float s = 0.f;
#pragma unroll 5
            for (int a = 0; a < A_; a++) s += g_embed[aidx[c*A_ + a]*64 + tid];
            sa[c][tid] = s * (1.f / A_);
        }
    } else {
        for (int i = tid - 64; i < 64*C_; i += 64) swp[i] = Wpred[i];
        if (tid - 64 < C_) sbp[tid - 64] = bpred[tid - 64];
    }
    __syncthreads();
    if (tid < C_) {
        float s = 0.f;
        for (int h = 0; h < 64; h++) { float v = sa[tid][h]; s += v*v; }
        sa2[tid] = s;
    }
    __syncthreads();
    int n = blockIdx.x * 128 + tid;
    float e[64];
    const float4* ep = (const float4*)(g_embed + n*64);
#pragma unroll
    for (int i = 0; i < 16; i++) {
        float4 v = ep[i];
        e[4*i] = v.x; e[4*i+1] = v.y; e[4*i+2] = v.z; e[4*i+3] = v.w;
    }
    float en2 = 0.f;
#pragma unroll
    for (int h = 0; h < 64; h++) en2 += e[h]*e[h];
    int best = 0; float bd = 3.4e38f;
    for (int c = 0; c < C_; c++) {
        float dot = 0.f;
#pragma unroll
        for (int h = 0; h < 64; h++) dot += e[h] * sa[c][h];
        float d2 = en2 - 2.f*dot + sa2[c];
        if (d2 < bd) { bd = d2; best = c; }
    }
    g_cls[n] = best;
    float xo[C_];
    for (int c = 0; c < C_; c++) {
        float s = sbp[c];
#pragma unroll
        for (int h = 0; h < 64; h++) s += e[h] * swp[h*C_ + c];
        xo[c] = s;
    }
    float m = xo[0];
    for (int c = 1; c < C_; c++) m = fmaxf(m, xo[c]);
    float se = 0.f;
    for (int c = 0; c < C_; c++) se += expf(xo[c] - m);
    float ls = logf(se);
    for (int c = 0; c < C_; c++) out[2*B_ + n*C_ + c] = xo[c] - m - ls;
}
__global__ __launch_bounds__(256) void k_cmean_f(
        const int* __restrict__ ego, const int* __restrict__ pos,
        const int* __restrict__ neg) {
    int q = blockIdx.x;
    int v = (q < B_) ? ego[q] : (q < 2*B_) ? pos[q - B_] : neg[q - 2*B_];
    __shared__ unsigned hop[NW_];
    __shared__ int list1[1024]; __shared__ int n1;
    __shared__ float sums[CH_]; __shared__ int cnt[C_];
    __shared__ int list[4096]; __shared__ int nlist;
    int tid = threadIdx.x;
    for (int i = tid; i < CH_; i += 256) sums[i] = 0.f;
    if (tid < C_) cnt[tid] = 0;
    if (tid == 0) { n1 = 0; nlist = 0; }
    if (tid < NW_) hop[tid] = g_adj[v*NW_ + tid];
    __syncthreads();
    if (tid < NW_) {
        unsigned bits = hop[tid];
        while (bits) { int b = __ffs(bits)-1; bits &= bits-1; list1[atomicAdd(&n1,1)] = tid*32+b; }
    }
    __syncthreads();
    int m1 = n1;
    if (tid < NW_) {
        unsigned acc = hop[tid];
        for (int j = 0; j < m1; j++) acc |= g_adj[list1[j]*NW_ + tid];
        hop[tid] = acc;
    }
    __syncthreads();
    if (tid < NW_) {
        unsigned bits = hop[tid];
        while (bits) { int b = __ffs(bits)-1; bits &= bits-1; list[atomicAdd(&nlist,1)] = tid*32+b; }
    }
    __syncthreads();
    int M = nlist, lane = tid & 31, warp = tid >> 5;
    for (int li = warp; li < M; li += 8) {
        int n = list[li]; int c = g_cls[n];
        atomicAdd(&sums[c*64 + lane],      g_embed[n*64 + lane]);
        atomicAdd(&sums[c*64 + lane + 32], g_embed[n*64 + lane + 32]);
        if (lane == 0) atomicAdd(&cnt[c], 1);
    }
    __syncthreads();
    for (int i = tid; i < CH_; i += 256) {
        int c = i >> 6;
        float cc = (float)(cnt[c] > 0 ? cnt[c] : 1);
        g_red[q*CH_ + i] = sums[i] / cc;
    }
}
__global__ void k_dec_f(const float* __restrict__ W1, const float* __restrict__ b1,
                        const float* __restrict__ W2, const float* __restrict__ b2,
                        float* __restrict__ out) {
    int b = blockIdx.x;
    __shared__ float op[CH_], on[CH_];
    __shared__ float part[4][32];
    int tid = threadIdx.x;
    const float* er = g_red + (size_t)b*CH_;
    const float* pr = g_red + (size_t)(B_ + b)*CH_;
    const float* nr = g_red + (size_t)(2*B_ + b)*CH_;
    for (int i = tid; i < CH_; i += 128) {
        float e = er[i];
        float dp = e - pr[i]; op[i] = dp*dp;
        float dn = e - nr[i]; on[i] = dn*dn;
    }
    __syncthreads();
    int lane = tid & 31, warp = tid >> 5;
    const float* o = (warp < 2) ? op : on;
    int i0 = (warp & 1) * 224;
    float h = 0.f;
    for (int i = i0; i < i0 + 224; i++) h += o[i] * W1[i*32 + lane];
    part[warp][lane] = h;
    __syncthreads();
    if (warp == 0 || warp == 2) {
        int pb = warp;
        float hv = part[pb][lane] + part[pb+1][lane] + b1[lane];
        hv = hv > 0.f ? hv : 0.f;
        float v = hv * W2[lane];
        for (int o2 = 16; o2 > 0; o2 >>= 1) v += __shfl_down_sync(0xffffffffu, v, o2);
        if (lane == 0) out[(warp == 0 ? b : B_ + b)] = v + b2[0];
    }
}

// ---------------- host config (static init; no device allocation) -----------
struct MegaCfg {
    int nb = 0;
    MegaCfg() {
        cudaFuncSetAttribute(k_mega, cudaFuncAttributePreferredSharedMemoryCarveout, 50);
        int sms = 0, bpm = 0;
        if (cudaDeviceGetAttribute(&sms, cudaDevAttrMultiProcessorCount, 0) != cudaSuccess) return;
        if (cudaOccupancyMaxActiveBlocksPerMultiprocessor(&bpm, k_mega, NT_, 0) != cudaSuccess) return;
        long t = (long)sms * bpm;
        if (t > 1024) t = 1024;
        if (t >= 48) nb = (int)t;
    }
};
static MegaCfg cfg;

// ---------------- launch ------------------------------------------------------
extern "C" void kernel_launch(void* const* d_in, const int* in_sizes, int n_in,
                              void* d_out, int out_size) {
    const float* x    = (const float*)d_in[0];
    const int*   ei   = (const int*)  d_in[1];
    const int*   ego  = (const int*)  d_in[2];
    const int*   pos  = (const int*)  d_in[3];
    const int*   neg  = (const int*)  d_in[4];
    const float* ew   = (const float*)d_in[5];
    const int*   aidx = (const int*)  d_in[6];
    int wb = (in_sizes[7] == FIN_*H_) ? 7 : 8;
    const float* Wenc  = (const float*)d_in[wb + 0];
    const float* benc  = (const float*)d_in[wb + 1];
    const float* Wpred = (const float*)d_in[wb + 2];
    const float* bpred = (const float*)d_in[wb + 3];
    const float* W1    = (const float*)d_in[wb + 4];
    const float* b1    = (const float*)d_in[wb + 5];
    const float* W2    = (const float*)d_in[wb + 6];
    const float* b2    = (const float*)d_in[wb + 7];
    float* out = (float*)d_out;

    if (cfg.nb > 0) {
        k_mega<<<cfg.nb, NT_>>>(x, ei, ego, pos, neg, ew, aidx,
                                Wenc, benc, Wpred, bpred, W1, b1, W2, b2,
                                out, cfg.nb);
    } else {
        k_hist_f   <<<256, 256>>>(ew);
        k_pick_f   <<<1, 1024>>>(ew, KSEL_);
        k_encoder_f<<<N_/32, 256>>>(x, Wenc, benc);
        k_adj_f    <<<(E_ + N_ + 255)/256, 256>>>(ei, ew);
        k_cls_f    <<<N_/128, 128>>>(aidx, Wpred, bpred, out);
        k_cmean_f  <<<3*B_, 256>>>(ego, pos, neg);
        k_dec_f    <<<B_, 128>>>(W1, b1, W2, b2, out);
    }
}

// round 8
// speedup vs baseline: 2.2053x; 2.2053x over previous
#include <cuda_runtime.h>
#include <cuda_bf16.h>

#define N_    4096
#define FIN_  500
#define H_    64
#define C_    7
#define E_    65536
#define B_    1024
#define A_    20
#define NW_   128          // bitset words per row
#define CH_   (C_*H_)      // 448
#define HB_   65536        // 16-bit histogram bins
#define CAP_  2048
#define KSEL_ (E_/2)
#define KB_   50
#define NSTG_ (FIN_/KB_)   // 10

// ---------------- scratch (device globals; zero at module load) -------------
__device__ float    g_embed[N_*H_];
__device__ unsigned g_adj[N_*NW_];
__device__ int      g_cls[N_];
__device__ float    g_thresh;
__device__ int      g_hist[HB_];

// ---------------- packed f32x2 helpers --------------------------------------
__device__ __forceinline__ unsigned long long pack2(float lo, float hi) {
    unsigned long long v;
    asm("mov.b64 %0, {%1, %2};" : "=l"(v) : "f"(lo), "f"(hi));
    return v;
}
__device__ __forceinline__ void unpack2(unsigned long long v, float& lo, float& hi) {
    asm("mov.b64 {%0, %1}, %2;" : "=f"(lo), "=f"(hi) : "l"(v));
}
__device__ __forceinline__ void fma2(unsigned long long& d,
                                     unsigned long long a, unsigned long long b) {
    asm("fma.rn.f32x2 %0, %1, %2, %0;" : "+l"(d) : "l"(a), "l"(b));
}

// ---------------- 1a) histogram (float4) + zero g_adj -----------------------
// g_hist arrives zeroed (module load on run 1, k_pick self-zero afterwards).
__global__ void k_hist(const float* __restrict__ w) {
    int i = blockIdx.x * blockDim.x + threadIdx.x;     // 16384 threads
    float4 wv = ((const float4*)w)[i];
    atomicAdd(&g_hist[__float_as_uint(wv.x) >> 16], 1);
    atomicAdd(&g_hist[__float_as_uint(wv.y) >> 16], 1);
    atomicAdd(&g_hist[__float_as_uint(wv.z) >> 16], 1);
    atomicAdd(&g_hist[__float_as_uint(wv.w) >> 16], 1);
    uint4 z = make_uint4(0u, 0u, 0u, 0u);
#pragma unroll
    for (int j = 0; j < 8; j++)
        ((uint4*)g_adj)[i + j*16384] = z;              // 131072 uint4 total
}

// ---------------- 1b) exact k-th largest (vectorized scans) -----------------
__global__ void k_pick(const float* __restrict__ w, int k) {
    __shared__ int s_scan[1024];
    __shared__ unsigned s_cand[CAP_];
    __shared__ int s_n, s_bucket, s_krem;
    int tid = threadIdx.x;
    const int CHK = 64;                     // bins per thread
    int abase = HB_ - (tid + 1) * CHK;      // ascending start of my chunk

    // chunk sum via int4
    int psum = 0;
    const int4* hp = (const int4*)(g_hist + abase);
#pragma unroll
    for (int i = 0; i < 16; i++) {
        int4 h4 = hp[i];
        psum += h4.x + h4.y + h4.z + h4.w;
    }
    s_scan[tid] = psum;
    __syncthreads();
    for (int off = 1; off < 1024; off <<= 1) {
        int v = (tid >= off) ? s_scan[tid - off] : 0;
        __syncthreads();
        s_scan[tid] += v;
        __syncthreads();
    }
    int incl = s_scan[tid];
    int excl = incl - psum;
    if (excl < k && incl >= k) {            // winner walks its chunk descending
        int cum = excl;
        int dbase = HB_ - 1 - tid * CHK;
        for (int i = 0; i < CHK; i++) {
            int b = dbase - i;
            int h = g_hist[b];
            cum += h;
            if (cum >= k) { s_bucket = b; s_krem = k - (cum - h); break; }
        }
    }
    if (tid == 0) s_n = 0;
    __syncthreads();
    // zero hist chunk for next replay (all reads done)
    int4 z4 = make_int4(0, 0, 0, 0);
#pragma unroll
    for (int i = 0; i < 16; i++) ((int4*)(g_hist + abase))[i] = z4;

    // candidate gather via uint4 (16 iterations, exact)
    int bucket = s_bucket;
    const uint4* wp = (const uint4*)w;
#pragma unroll 4
    for (int i = tid; i < E_/4; i += 1024) {
        uint4 k4 = wp[i];
        unsigned kk;
        kk = k4.x; if ((int)(kk >> 16) == bucket) { int p = atomicAdd(&s_n, 1); if (p < CAP_) s_cand[p] = kk; }
        kk = k4.y; if ((int)(kk >> 16) == bucket) { int p = atomicAdd(&s_n, 1); if (p < CAP_) s_cand[p] = kk; }
        kk = k4.z; if ((int)(kk >> 16) == bucket) { int p = atomicAdd(&s_n, 1); if (p < CAP_) s_cand[p] = kk; }
        kk = k4.w; if ((int)(kk >> 16) == bucket) { int p = atomicAdd(&s_n, 1); if (p < CAP_) s_cand[p] = kk; }
    }
    __syncthreads();
    int n = s_n < CAP_ ? s_n : CAP_;
    int krem = s_krem;
    for (int i = tid; i < n; i += 1024) {
        unsigned v = s_cand[i];
        int gt = 0, eq = 0;
        for (int j = 0; j < n; j++) {
            unsigned u = s_cand[j];
            gt += (u > v); eq += (u == v);
        }
        if (gt < krem && krem <= gt + eq)
            g_thresh = __uint_as_float(v);
    }
}

// ---------------- 2) encoder: 16-row x 64-col tiles, grid 256 ---------------
// thread = 1 row x 4 cols (row = tid&15, broadcast W reads), double-buffered.
__global__ __launch_bounds__(256) void k_encoder(
        const float* __restrict__ x,
        const float* __restrict__ Wenc,
        const float* __restrict__ benc) {
    __shared__ float xs[2][KB_][17];
    __shared__ float ws[2][KB_][64];
    int tid = threadIdx.x;
    int row = tid & 15;
    int c0  = (tid >> 4) * 4;
    int r0  = blockIdx.x * 16;

    unsigned long long acc0 = 0ull, acc1 = 0ull;
    float xr[4]; float4 wr[4];

    {   // prologue: stage 0 (x: 800 scalars, w: 800 float4)
#pragma unroll
        for (int j = 0; j < 4; j++) {
            int i = tid + j*256;
            if (i < 800) {
                xr[j] = x[(r0 + i/KB_)*FIN_ + (i % KB_)];
                wr[j] = *(const float4*)&Wenc[(i >> 4)*H_ + (i & 15)*4];
            }
        }
#pragma unroll
        for (int j = 0; j < 4; j++) {
            int i = tid + j*256;
            if (i < 800) {
                xs[0][i % KB_][i / KB_] = xr[j];
                *(float4*)&ws[0][i >> 4][(i & 15)*4] = wr[j];
            }
        }
    }
    __syncthreads();

    for (int s = 0; s < NSTG_; s++) {
        int buf = s & 1;
        if (s + 1 < NSTG_) {
            int k0 = (s + 1) * KB_;
#pragma unroll
            for (int j = 0; j < 4; j++) {
                int i = tid + j*256;
                if (i < 800) {
                    xr[j] = x[(r0 + i/KB_)*FIN_ + k0 + (i % KB_)];
                    wr[j] = *(const float4*)&Wenc[(k0 + (i >> 4))*H_ + (i & 15)*4];
                }
            }
        }
#pragma unroll 10
        for (int kk = 0; kk < KB_; kk++) {
            float a = xs[buf][kk][row];
            unsigned long long aa = pack2(a, a);
            float4 bv = *(const float4*)&ws[buf][kk][c0];
            fma2(acc0, aa, pack2(bv.x, bv.y));
            fma2(acc1, aa, pack2(bv.z, bv.w));
        }
        if (s + 1 < NSTG_) {
            int nb = buf ^ 1;
#pragma unroll
            for (int j = 0; j < 4; j++) {
                int i = tid + j*256;
                if (i < 800) {
                    xs[nb][i % KB_][i / KB_] = xr[j];
                    *(float4*)&ws[nb][i >> 4][(i & 15)*4] = wr[j];
                }
            }
        }
        __syncthreads();
    }
    float v0, v1, v2, v3;
    unpack2(acc0, v0, v1); unpack2(acc1, v2, v3);
    v0 += benc[c0];   v1 += benc[c0+1];
    v2 += benc[c0+2]; v3 += benc[c0+3];
    *(float4*)&g_embed[(r0 + row)*H_ + c0] =
        make_float4(fmaxf(v0,0.f), fmaxf(v1,0.f), fmaxf(v2,0.f), fmaxf(v3,0.f));
}

// ---------------- 3) adjacency bitset ---------------------------------------
__global__ void k_adj(const int* __restrict__ ei, const float* __restrict__ ew) {
    int i = blockIdx.x * blockDim.x + threadIdx.x;
    float th = g_thresh;
    if (i < E_) {
        if (ew[i] >= th) {
            int s = ei[i], d = ei[E_ + i];
            atomicOr(&g_adj[s*NW_ + (d >> 5)], 1u << (d & 31));
        }
    } else if (i < E_ + N_) {
        int n = i - E_;
        atomicOr(&g_adj[n*NW_ + (n >> 5)], 1u << (n & 31));   // diag
    }
}

// ---------------- 4) anchors (in-block) + class assign + log_softmax --------
__global__ void k_cls(const int* __restrict__ aidx,
                      const float* __restrict__ Wpred,
                      const float* __restrict__ bpred,
                      float* __restrict__ out) {
    __shared__ float sa[C_][64];
    __shared__ float sa2[C_];
    __shared__ float swp[64*C_];
    __shared__ float sbp[C_];
    int tid = threadIdx.x;           // 128
    if (tid < 64) {
        for (int c = 0; c < C_; c++) {
            float s = 0.f;
#pragma unroll 5
            for (int a = 0; a < A_; a++)
                s += g_embed[aidx[c*A_ + a]*64 + tid];
            sa[c][tid] = s * (1.f / A_);
        }
    } else {
        for (int i = tid - 64; i < 64*C_; i += 64) swp[i] = Wpred[i];
        if (tid - 64 < C_) sbp[tid - 64] = bpred[tid - 64];
    }
    __syncthreads();
    if (tid < C_) {
        float s = 0.f;
        for (int h = 0; h < 64; h++) { float v = sa[tid][h]; s += v*v; }
        sa2[tid] = s;
    }
    __syncthreads();

    int n = blockIdx.x * 128 + tid;
    float e[64];
    const float4* ep = (const float4*)(g_embed + n*64);
#pragma unroll
    for (int i = 0; i < 16; i++) {
        float4 v = ep[i];
        e[4*i] = v.x; e[4*i+1] = v.y; e[4*i+2] = v.z; e[4*i+3] = v.w;
    }
    float en2 = 0.f;
#pragma unroll
    for (int h = 0; h < 64; h++) en2 += e[h]*e[h];
    int best = 0; float bd = 3.4e38f;
    for (int c = 0; c < C_; c++) {
        float dot = 0.f;
#pragma unroll
        for (int h = 0; h < 64; h++) dot += e[h] * sa[c][h];
        float d2 = en2 - 2.f*dot + sa2[c];
        if (d2 < bd) { bd = d2; best = c; }
    }
    g_cls[n] = best;
    float xo[C_];
    for (int c = 0; c < C_; c++) {
        float s = sbp[c];
#pragma unroll
        for (int h = 0; h < 64; h++) s += e[h] * swp[h*C_ + c];
        xo[c] = s;
    }
    float m = xo[0];
    for (int c = 1; c < C_; c++) m = fmaxf(m, xo[c]);
    float se = 0.f;
    for (int c = 0; c < C_; c++) se += expf(xo[c] - m);
    float ls = logf(se);
    for (int c = 0; c < C_; c++) out[2*B_ + n*C_ + c] = xo[c] - m - ls;
}

// ---------------- 5) fused 2-hop + class-mean triplet + decoder --------------
// One block per (ego,pos,neg) triplet: builds the 2-hop class-means for all
// three queries in shared, then runs the MLP decoder inline. No g_red.
__global__ __launch_bounds__(256) void k_cmean_dec(
        const int* __restrict__ ego, const int* __restrict__ pos,
        const int* __restrict__ neg,
        const float* __restrict__ W1, const float* __restrict__ b1,
        const float* __restrict__ W2, const float* __restrict__ b2,
        float* __restrict__ out) {
    __shared__ unsigned hop[NW_];
    __shared__ int   list1[1024];
    __shared__ int   list[4096];      // node | (cls<<12)
    __shared__ float sums[3][CH_];
    __shared__ int   cnt[3][C_];
    __shared__ int   n1, nlist;
    __shared__ float op[CH_], on[CH_];
    __shared__ float part[8][32];

    int b = blockIdx.x;
    int tid = threadIdx.x;            // 256
    int lane = tid & 31, warp = tid >> 5;

    for (int t = 0; t < 3; t++) {
        int v = (t == 0) ? ego[b] : (t == 1) ? pos[b] : neg[b];
        for (int i = tid; i < CH_; i += 256) sums[t][i] = 0.f;
        if (tid < C_) cnt[t][tid] = 0;
        if (tid == 0) { n1 = 0; nlist = 0; }
        if (tid < NW_) hop[tid] = g_adj[v*NW_ + tid];
        __syncthreads();

        // 1-hop neighbor list (parallel per word)
        if (tid < NW_) {
            unsigned bits = hop[tid];
            while (bits) {
                int bb = __ffs(bits) - 1; bits &= bits - 1;
                list1[atomicAdd(&n1, 1)] = tid*32 + bb;
            }
        }
        __syncthreads();
        int m1 = n1;

        // OR neighbor rows: warp-strided neighbors, uint4 row chunks, smem atomicOr
        for (int j = warp; j < m1; j += 8) {
            const uint4* rp = (const uint4*)&g_adj[list1[j]*NW_];
            uint4 r4 = rp[lane];      // lane covers words [lane*4, lane*4+4)
            if (r4.x) atomicOr(&hop[lane*4 + 0], r4.x);
            if (r4.y) atomicOr(&hop[lane*4 + 1], r4.y);
            if (r4.z) atomicOr(&hop[lane*4 + 2], r4.z);
            if (r4.w) atomicOr(&hop[lane*4 + 3], r4.w);
        }
        __syncthreads();

        // 2-hop member list, with class packed in (breaks gather dep chain)
        if (tid < NW_) {
            unsigned bits = hop[tid];
            while (bits) {
                int bb = __ffs(bits) - 1; bits &= bits - 1;
                int node = tid*32 + bb;
                list[atomicAdd(&nlist, 1)] = node | (g_cls[node] << 12);
            }
        }
        __syncthreads();

        int M = nlist;
        for (int li = warp; li < M; li += 8) {
            int e = list[li];
            int n = e & 0xFFF, c = e >> 12;
            float2 e2 = *(const float2*)&g_embed[n*H_ + lane*2];
            atomicAdd(&sums[t][c*H_ + lane*2],     e2.x);
            atomicAdd(&sums[t][c*H_ + lane*2 + 1], e2.y);
            if (lane == 0) atomicAdd(&cnt[t][c], 1);
        }
        __syncthreads();
    }

    // squared differences
    for (int i = tid; i < CH_; i += 256) {
        int c = i >> 6;
        float ce = (float)max(cnt[0][c], 1);
        float cp = (float)max(cnt[1][c], 1);
        float cn = (float)max(cnt[2][c], 1);
        float e  = sums[0][i] / ce;
        float p  = sums[1][i] / cp;
        float nn = sums[2][i] / cn;
        float dp = e - p, dn = e - nn;
        op[i] = dp*dp;
        on[i] = dn*dn;
    }
    __syncthreads();

    // decoder: warps 0-3 -> pos branch, 4-7 -> neg branch (112 rows each)
    {
        const float* o = (warp < 4) ? op : on;
        int i0 = (warp & 3) * 112;
        float h = 0.f;
        for (int i = i0; i < i0 + 112; i++)
            h += o[i] * W1[i*32 + lane];
        part[warp][lane] = h;
    }
    __syncthreads();
    if (warp == 0 || warp == 4) {
        int pb = warp;
        float hv = part[pb][lane] + part[pb+1][lane]
                 + part[pb+2][lane] + part[pb+3][lane] + b1[lane];
        hv = fmaxf(hv, 0.f);
        float vv = hv * W2[lane];
#pragma unroll
        for (int o2 = 16; o2 > 0; o2 >>= 1)
            vv += __shfl_down_sync(0xffffffffu, vv, o2);
        if (lane == 0) out[(warp == 0) ? b : (B_ + b)] = vv + b2[0];
    }
}

// ---------------- stream fork resources (host-side, created at load) --------
struct HxStreams {
    cudaStream_t s2 = nullptr;
    cudaEvent_t  fork = nullptr, join = nullptr;
    bool ok = false;
    HxStreams() {
        if (cudaStreamCreateWithFlags(&s2, cudaStreamNonBlocking) != cudaSuccess) return;
        if (cudaEventCreateWithFlags(&fork, cudaEventDisableTiming) != cudaSuccess) return;
        if (cudaEventCreateWithFlags(&join, cudaEventDisableTiming) != cudaSuccess) return;
        ok = true;
    }
};
static HxStreams hx;

// ---------------- launch ------------------------------------------------------
extern "C" void kernel_launch(void* const* d_in, const int* in_sizes, int n_in,
                              void* d_out, int out_size) {
    const float* x    = (const float*)d_in[0];
    const int*   ei   = (const int*)  d_in[1];
    const int*   ego  = (const int*)  d_in[2];
    const int*   pos  = (const int*)  d_in[3];
    const int*   neg  = (const int*)  d_in[4];
    const float* ew   = (const float*)d_in[5];
    const int*   aidx = (const int*)  d_in[6];
    int wb = (in_sizes[7] == FIN_*H_) ? 7 : 8;
    const float* Wenc  = (const float*)d_in[wb + 0];
    const float* benc  = (const float*)d_in[wb + 1];
    const float* Wpred = (const float*)d_in[wb + 2];
    const float* bpred = (const float*)d_in[wb + 3];
    const float* W1    = (const float*)d_in[wb + 4];
    const float* b1    = (const float*)d_in[wb + 5];
    const float* W2    = (const float*)d_in[wb + 6];
    const float* b2    = (const float*)d_in[wb + 7];
    float* out = (float*)d_out;

    if (hx.ok) {
        cudaEventRecord(hx.fork, 0);
        cudaStreamWaitEvent(hx.s2, hx.fork, 0);

        k_hist <<<64, 256>>>(ew);
        k_pick <<<1, 1024>>>(ew, KSEL_);
        k_adj  <<<(E_ + N_ + 255)/256, 256>>>(ei, ew);

        k_encoder<<<N_/16, 256, 0, hx.s2>>>(x, Wenc, benc);
        k_cls    <<<N_/128, 128, 0, hx.s2>>>(aidx, Wpred, bpred, out);
        cudaEventRecord(hx.join, hx.s2);
        cudaStreamWaitEvent(0, hx.join, 0);

        k_cmean_dec<<<B_, 256>>>(ego, pos, neg, W1, b1, W2, b2, out);
    } else {
        k_hist   <<<64, 256>>>(ew);
        k_pick   <<<1, 1024>>>(ew, KSEL_);
        k_encoder<<<N_/16, 256>>>(x, Wenc, benc);
        k_adj    <<<(E_ + N_ + 255)/256, 256>>>(ei, ew);
        k_cls    <<<N_/128, 128>>>(aidx, Wpred, bpred, out);
        k_cmean_dec<<<B_, 256>>>(ego, pos, neg, W1, b1, W2, b2, out);
    }
}

// round 9
// speedup vs baseline: 2.2211x; 1.0072x over previous
#include <cuda_runtime.h>
#include <cuda_bf16.h>

#define N_    4096
#define FIN_  500
#define H_    64
#define C_    7
#define E_    65536
#define B_    1024
#define A_    20
#define NW_   128          // bitset words per row
#define CH_   (C_*H_)      // 448
#define HB_   65536        // 16-bit histogram bins
#define CAP_  2048
#define KSEL_ (E_/2)
#define KB_   50
#define NSTG_ (FIN_/KB_)   // 10

// ---------------- scratch (device globals; zero at module load) -------------
__device__ float    g_embed[N_*H_];
__device__ unsigned g_adj[N_*NW_];
__device__ int      g_cls[N_];
__device__ float    g_thresh;
__device__ int      g_hist[HB_];

// ---------------- packed f32x2 helpers --------------------------------------
__device__ __forceinline__ unsigned long long pack2(float lo, float hi) {
    unsigned long long v;
    asm("mov.b64 %0, {%1, %2};" : "=l"(v) : "f"(lo), "f"(hi));
    return v;
}
__device__ __forceinline__ void unpack2(unsigned long long v, float& lo, float& hi) {
    asm("mov.b64 {%0, %1}, %2;" : "=f"(lo), "=f"(hi) : "l"(v));
}
__device__ __forceinline__ void fma2(unsigned long long& d,
                                     unsigned long long a, unsigned long long b) {
    asm("fma.rn.f32x2 %0, %1, %2, %0;" : "+l"(d) : "l"(a), "l"(b));
}

// ---------------- 1a) histogram (float4) + zero g_adj -----------------------
__global__ void k_hist(const float* __restrict__ w) {
    int i = blockIdx.x * blockDim.x + threadIdx.x;     // 16384 threads
    float4 wv = ((const float4*)w)[i];
    atomicAdd(&g_hist[__float_as_uint(wv.x) >> 16], 1);
    atomicAdd(&g_hist[__float_as_uint(wv.y) >> 16], 1);
    atomicAdd(&g_hist[__float_as_uint(wv.z) >> 16], 1);
    atomicAdd(&g_hist[__float_as_uint(wv.w) >> 16], 1);
    uint4 z = make_uint4(0u, 0u, 0u, 0u);
#pragma unroll
    for (int j = 0; j < 8; j++)
        ((uint4*)g_adj)[i + j*16384] = z;              // 131072 uint4 total
}

// ---------------- 1b) exact k-th largest (vectorized scans) -----------------
__global__ void k_pick(const float* __restrict__ w, int k) {
    __shared__ int s_scan[1024];
    __shared__ unsigned s_cand[CAP_];
    __shared__ int s_n, s_bucket, s_krem;
    int tid = threadIdx.x;
    const int CHK = 64;
    int abase = HB_ - (tid + 1) * CHK;

    int psum = 0;
    const int4* hp = (const int4*)(g_hist + abase);
#pragma unroll
    for (int i = 0; i < 16; i++) {
        int4 h4 = hp[i];
        psum += h4.x + h4.y + h4.z + h4.w;
    }
    s_scan[tid] = psum;
    __syncthreads();
    for (int off = 1; off < 1024; off <<= 1) {
        int v = (tid >= off) ? s_scan[tid - off] : 0;
        __syncthreads();
        s_scan[tid] += v;
        __syncthreads();
    }
    int incl = s_scan[tid];
    int excl = incl - psum;
    if (excl < k && incl >= k) {
        int cum = excl;
        int dbase = HB_ - 1 - tid * CHK;
        for (int i = 0; i < CHK; i++) {
            int b = dbase - i;
            int h = g_hist[b];
            cum += h;
            if (cum >= k) { s_bucket = b; s_krem = k - (cum - h); break; }
        }
    }
    if (tid == 0) s_n = 0;
    __syncthreads();
    int4 z4 = make_int4(0, 0, 0, 0);
#pragma unroll
    for (int i = 0; i < 16; i++) ((int4*)(g_hist + abase))[i] = z4;

    int bucket = s_bucket;
    const uint4* wp = (const uint4*)w;
#pragma unroll 4
    for (int i = tid; i < E_/4; i += 1024) {
        uint4 k4 = wp[i];
        unsigned kk;
        kk = k4.x; if ((int)(kk >> 16) == bucket) { int p = atomicAdd(&s_n, 1); if (p < CAP_) s_cand[p] = kk; }
        kk = k4.y; if ((int)(kk >> 16) == bucket) { int p = atomicAdd(&s_n, 1); if (p < CAP_) s_cand[p] = kk; }
        kk = k4.z; if ((int)(kk >> 16) == bucket) { int p = atomicAdd(&s_n, 1); if (p < CAP_) s_cand[p] = kk; }
        kk = k4.w; if ((int)(kk >> 16) == bucket) { int p = atomicAdd(&s_n, 1); if (p < CAP_) s_cand[p] = kk; }
    }
    __syncthreads();
    int n = s_n < CAP_ ? s_n : CAP_;
    int krem = s_krem;
    for (int i = tid; i < n; i += 1024) {
        unsigned v = s_cand[i];
        int gt = 0, eq = 0;
        for (int j = 0; j < n; j++) {
            unsigned u = s_cand[j];
            gt += (u > v); eq += (u == v);
        }
        if (gt < krem && krem <= gt + eq)
            g_thresh = __uint_as_float(v);
    }
}

// ---------------- 2) encoder: 16x64 tiles, float2 a-loads -------------------
// xs row-major stride 50: rows 0..15 hit 16 distinct banks (18r mod 32),
// kk-pairs read as one LDS.64. Per 2kk: 1 LDS.64 + 2 LDS.128(bcast) + 4 FFMA2.
__global__ __launch_bounds__(256, 2) void k_encoder(
        const float* __restrict__ x,
        const float* __restrict__ Wenc,
        const float* __restrict__ benc) {
    __shared__ __align__(16) float xs[2][16][KB_];   // [buf][row][kk]
    __shared__ __align__(16) float ws[2][KB_][64];
    int tid = threadIdx.x;
    int row = tid & 15;
    int c0  = (tid >> 4) * 4;
    int r0  = blockIdx.x * 16;

    unsigned long long acc0 = 0ull, acc1 = 0ull;
    float xr[4]; float4 wr[4];

    {   // prologue: stage 0 (x: 800 scalars, w: 800 float4)
#pragma unroll
        for (int j = 0; j < 4; j++) {
            int i = tid + j*256;
            if (i < 800) {
                xr[j] = x[(r0 + i/KB_)*FIN_ + (i % KB_)];
                wr[j] = *(const float4*)&Wenc[(i >> 4)*H_ + (i & 15)*4];
            }
        }
#pragma unroll
        for (int j = 0; j < 4; j++) {
            int i = tid + j*256;
            if (i < 800) {
                xs[0][i / KB_][i % KB_] = xr[j];
                *(float4*)&ws[0][i >> 4][(i & 15)*4] = wr[j];
            }
        }
    }
    __syncthreads();

    for (int s = 0; s < NSTG_; s++) {
        int buf = s & 1;
        if (s + 1 < NSTG_) {
            int k0 = (s + 1) * KB_;
#pragma unroll
            for (int j = 0; j < 4; j++) {
                int i = tid + j*256;
                if (i < 800) {
                    xr[j] = x[(r0 + i/KB_)*FIN_ + k0 + (i % KB_)];
                    wr[j] = *(const float4*)&Wenc[(k0 + (i >> 4))*H_ + (i & 15)*4];
                }
            }
        }
#pragma unroll 5
        for (int kk2 = 0; kk2 < KB_/2; kk2++) {
            float2 ap = *(const float2*)&xs[buf][row][2*kk2];
            unsigned long long aa0 = pack2(ap.x, ap.x);
            unsigned long long aa1 = pack2(ap.y, ap.y);
            float4 b0 = *(const float4*)&ws[buf][2*kk2][c0];
            float4 b1 = *(const float4*)&ws[buf][2*kk2 + 1][c0];
            fma2(acc0, aa0, pack2(b0.x, b0.y));
            fma2(acc1, aa0, pack2(b0.z, b0.w));
            fma2(acc0, aa1, pack2(b1.x, b1.y));
            fma2(acc1, aa1, pack2(b1.z, b1.w));
        }
        if (s + 1 < NSTG_) {
            int nb = buf ^ 1;
#pragma unroll
            for (int j = 0; j < 4; j++) {
                int i = tid + j*256;
                if (i < 800) {
                    xs[nb][i / KB_][i % KB_] = xr[j];
                    *(float4*)&ws[nb][i >> 4][(i & 15)*4] = wr[j];
                }
            }
        }
        __syncthreads();
    }
    float v0, v1, v2, v3;
    unpack2(acc0, v0, v1); unpack2(acc1, v2, v3);
    v0 += benc[c0];   v1 += benc[c0+1];
    v2 += benc[c0+2]; v3 += benc[c0+3];
    *(float4*)&g_embed[(r0 + row)*H_ + c0] =
        make_float4(fmaxf(v0,0.f), fmaxf(v1,0.f), fmaxf(v2,0.f), fmaxf(v3,0.f));
}

// ---------------- 3) adjacency bitset ---------------------------------------
__global__ void k_adj(const int* __restrict__ ei, const float* __restrict__ ew) {
    int i = blockIdx.x * blockDim.x + threadIdx.x;
    float th = g_thresh;
    if (i < E_) {
        if (ew[i] >= th) {
            int s = ei[i], d = ei[E_ + i];
            atomicOr(&g_adj[s*NW_ + (d >> 5)], 1u << (d & 31));
        }
    } else if (i < E_ + N_) {
        int n = i - E_;
        atomicOr(&g_adj[n*NW_ + (n >> 5)], 1u << (n & 31));   // diag
    }
}

// ---------------- 4) anchors (in-block) + class assign + log_softmax --------
__global__ void k_cls(const int* __restrict__ aidx,
                      const float* __restrict__ Wpred,
                      const float* __restrict__ bpred,
                      float* __restrict__ out) {
    __shared__ float sa[C_][64];
    __shared__ float sa2[C_];
    __shared__ float swp[64*C_];
    __shared__ float sbp[C_];
    int tid = threadIdx.x;           // 128
    if (tid < 64) {
        for (int c = 0; c < C_; c++) {
            float s = 0.f;
#pragma unroll 5
            for (int a = 0; a < A_; a++)
                s += g_embed[aidx[c*A_ + a]*64 + tid];
            sa[c][tid] = s * (1.f / A_);
        }
    } else {
        for (int i = tid - 64; i < 64*C_; i += 64) swp[i] = Wpred[i];
        if (tid - 64 < C_) sbp[tid - 64] = bpred[tid - 64];
    }
    __syncthreads();
    if (tid < C_) {
        float s = 0.f;
        for (int h = 0; h < 64; h++) { float v = sa[tid][h]; s += v*v; }
        sa2[tid] = s;
    }
    __syncthreads();

    int n = blockIdx.x * 128 + tid;
    float e[64];
    const float4* ep = (const float4*)(g_embed + n*64);
#pragma unroll
    for (int i = 0; i < 16; i++) {
        float4 v = ep[i];
        e[4*i] = v.x; e[4*i+1] = v.y; e[4*i+2] = v.z; e[4*i+3] = v.w;
    }
    float en2 = 0.f;
#pragma unroll
    for (int h = 0; h < 64; h++) en2 += e[h]*e[h];
    int best = 0; float bd = 3.4e38f;
    for (int c = 0; c < C_; c++) {
        float dot = 0.f;
#pragma unroll
        for (int h = 0; h < 64; h++) dot += e[h] * sa[c][h];
        float d2 = en2 - 2.f*dot + sa2[c];
        if (d2 < bd) { bd = d2; best = c; }
    }
    g_cls[n] = best;
    float xo[C_];
    for (int c = 0; c < C_; c++) {
        float s = sbp[c];
#pragma unroll
        for (int h = 0; h < 64; h++) s += e[h] * swp[h*C_ + c];
        xo[c] = s;
    }
    float m = xo[0];
    for (int c = 1; c < C_; c++) m = fmaxf(m, xo[c]);
    float se = 0.f;
    for (int c = 0; c < C_; c++) se += expf(xo[c] - m);
    float ls = logf(se);
    for (int c = 0; c < C_; c++) out[2*B_ + n*C_ + c] = xo[c] - m - ls;
}

// ---------------- 5) fused 2-hop + class-mean + decoder, 3 queries parallel --
// 384 threads = 3 groups of 128; group t builds query t's class-mean using
// named barrier t+1 (no cross-group serialization), then one block-wide sync
// and the decoder MLP.
#define L1CAP_ 512
#define L2CAP_ 1536
__device__ __forceinline__ void barg(int t) {
    asm volatile("bar.sync %0, 128;" :: "r"(t + 1) : "memory");
}
__global__ __launch_bounds__(384) void k_cmean_dec(
        const int* __restrict__ ego, const int* __restrict__ pos,
        const int* __restrict__ neg,
        const float* __restrict__ W1, const float* __restrict__ b1,
        const float* __restrict__ W2, const float* __restrict__ b2,
        float* __restrict__ out) {
    __shared__ unsigned hop[3][NW_];
    __shared__ int   list1[3][L1CAP_];
    __shared__ int   list[3][L2CAP_];     // node | (cls<<12)
    __shared__ float sums[3][CH_];
    __shared__ int   cnt[3][C_];
    __shared__ int   n1[3], nlist[3];
    __shared__ float op[CH_], on[CH_];
    __shared__ float part[8][32];

    int b = blockIdx.x;
    int tid = threadIdx.x;            // 384
    int t   = tid >> 7;               // query group 0..2
    int gt  = tid & 127;              // id within group
    int gw  = gt >> 5;                // warp within group 0..3
    int lane = tid & 31;

    int v = (t == 0) ? ego[b] : (t == 1) ? pos[b] : neg[b];
    for (int i = gt; i < CH_; i += 128) sums[t][i] = 0.f;
    if (gt < C_) cnt[t][gt] = 0;
    if (gt == 0) { n1[t] = 0; nlist[t] = 0; }
    hop[t][gt] = g_adj[v*NW_ + gt];
    barg(t);

    // 1-hop neighbor list (parallel per word)
    {
        unsigned bits = hop[t][gt];
        while (bits) {
            int bb = __ffs(bits) - 1; bits &= bits - 1;
            int p = atomicAdd(&n1[t], 1);
            if (p < L1CAP_) list1[t][p] = gt*32 + bb;
        }
    }
    barg(t);
    int m1 = n1[t]; if (m1 > L1CAP_) m1 = L1CAP_;

    // OR neighbor rows (warp-strided, uint4, smem atomicOr)
    for (int j = gw; j < m1; j += 4) {
        const uint4* rp = (const uint4*)&g_adj[list1[t][j]*NW_];
        uint4 r4 = rp[lane];
        if (r4.x) atomicOr(&hop[t][lane*4 + 0], r4.x);
        if (r4.y) atomicOr(&hop[t][lane*4 + 1], r4.y);
        if (r4.z) atomicOr(&hop[t][lane*4 + 2], r4.z);
        if (r4.w) atomicOr(&hop[t][lane*4 + 3], r4.w);
    }
    barg(t);

    // 2-hop member list with class packed in
    {
        unsigned bits = hop[t][gt];
        while (bits) {
            int bb = __ffs(bits) - 1; bits &= bits - 1;
            int node = gt*32 + bb;
            int p = atomicAdd(&nlist[t], 1);
            if (p < L2CAP_) list[t][p] = node | (g_cls[node] << 12);
        }
    }
    barg(t);

    int M = nlist[t]; if (M > L2CAP_) M = L2CAP_;
    for (int li = gw; li < M; li += 4) {
        int e = list[t][li];
        int n = e & 0xFFF, c = e >> 12;
        float2 e2 = *(const float2*)&g_embed[n*H_ + lane*2];
        atomicAdd(&sums[t][c*H_ + lane*2],     e2.x);
        atomicAdd(&sums[t][c*H_ + lane*2 + 1], e2.y);
        if (lane == 0) atomicAdd(&cnt[t][c], 1);
    }
    __syncthreads();   // all three groups done

    // squared differences (all 384 threads)
    for (int i = tid; i < CH_; i += 384) {
        int c = i >> 6;
        float ce = (float)max(cnt[0][c], 1);
        float cp = (float)max(cnt[1][c], 1);
        float cn = (float)max(cnt[2][c], 1);
        float e  = sums[0][i] / ce;
        float p  = sums[1][i] / cp;
        float nn = sums[2][i] / cn;
        float dp = e - p, dn = e - nn;
        op[i] = dp*dp;
        on[i] = dn*dn;
    }
    __syncthreads();

    // decoder: warps 0-3 -> pos branch, 4-7 -> neg branch (112 rows each)
    int warp = tid >> 5;
    if (warp < 8) {
        const float* o = (warp < 4) ? op : on;
        int i0 = (warp & 3) * 112;
        float h = 0.f;
        for (int i = i0; i < i0 + 112; i++)
            h += o[i] * W1[i*32 + lane];
        part[warp][lane] = h;
    }
    __syncthreads();
    if (warp == 0 || warp == 4) {
        int pb = warp;
        float hv = part[pb][lane] + part[pb+1][lane]
                 + part[pb+2][lane] + part[pb+3][lane] + b1[lane];
        hv = fmaxf(hv, 0.f);
        float vv = hv * W2[lane];
#pragma unroll
        for (int o2 = 16; o2 > 0; o2 >>= 1)
            vv += __shfl_down_sync(0xffffffffu, vv, o2);
        if (lane == 0) out[(warp == 0) ? b : (B_ + b)] = vv + b2[0];
    }
}

// ---------------- stream fork resources (host-side, created at load) --------
struct HxStreams {
    cudaStream_t s2 = nullptr;
    cudaEvent_t  fork = nullptr, join = nullptr;
    bool ok = false;
    HxStreams() {
        if (cudaStreamCreateWithFlags(&s2, cudaStreamNonBlocking) != cudaSuccess) return;
        if (cudaEventCreateWithFlags(&fork, cudaEventDisableTiming) != cudaSuccess) return;
        if (cudaEventCreateWithFlags(&join, cudaEventDisableTiming) != cudaSuccess) return;
        ok = true;
    }
};
static HxStreams hx;

// ---------------- launch ------------------------------------------------------
extern "C" void kernel_launch(void* const* d_in, const int* in_sizes, int n_in,
                              void* d_out, int out_size) {
    const float* x    = (const float*)d_in[0];
    const int*   ei   = (const int*)  d_in[1];
    const int*   ego  = (const int*)  d_in[2];
    const int*   pos  = (const int*)  d_in[3];
    const int*   neg  = (const int*)  d_in[4];
    const float* ew   = (const float*)d_in[5];
    const int*   aidx = (const int*)  d_in[6];
    int wb = (in_sizes[7] == FIN_*H_) ? 7 : 8;
    const float* Wenc  = (const float*)d_in[wb + 0];
    const float* benc  = (const float*)d_in[wb + 1];
    const float* Wpred = (const float*)d_in[wb + 2];
    const float* bpred = (const float*)d_in[wb + 3];
    const float* W1    = (const float*)d_in[wb + 4];
    const float* b1    = (const float*)d_in[wb + 5];
    const float* W2    = (const float*)d_in[wb + 6];
    const float* b2    = (const float*)d_in[wb + 7];
    float* out = (float*)d_out;

    if (hx.ok) {
        cudaEventRecord(hx.fork, 0);
        cudaStreamWaitEvent(hx.s2, hx.fork, 0);

        k_hist <<<64, 256>>>(ew);
        k_pick <<<1, 1024>>>(ew, KSEL_);
        k_adj  <<<(E_ + N_ + 255)/256, 256>>>(ei, ew);

        k_encoder<<<N_/16, 256, 0, hx.s2>>>(x, Wenc, benc);
        k_cls    <<<N_/128, 128, 0, hx.s2>>>(aidx, Wpred, bpred, out);
        cudaEventRecord(hx.join, hx.s2);
        cudaStreamWaitEvent(0, hx.join, 0);

        k_cmean_dec<<<B_, 384>>>(ego, pos, neg, W1, b1, W2, b2, out);
    } else {
        k_hist   <<<64, 256>>>(ew);
        k_pick   <<<1, 1024>>>(ew, KSEL_);
        k_encoder<<<N_/16, 256>>>(x, Wenc, benc);
        k_adj    <<<(E_ + N_ + 255)/256, 256>>>(ei, ew);
        k_cls    <<<N_/128, 128>>>(aidx, Wpred, bpred, out);
        k_cmean_dec<<<B_, 384>>>(ego, pos, neg, W1, b1, W2, b2, out);
    }
}